// round 5
// baseline (speedup 1.0000x reference)
#include <cuda_runtime.h>
#include <math.h>
#include <stdint.h>

#define NNODES 50000
#define TT 8
#define HH 128
#define COUT 32
#define EDGES 800000
#define MROWS 400000

// ======================= scratch (device globals) ============================
__device__ int   g_is64;
__device__ int   g_src[EDGES];
__device__ int   g_dst[EDGES];
__device__ int   g_cnt[NNODES];
__device__ int   g_off[NNODES];
__device__ int   g_cur[NNODES];
__device__ int   g_adj[EDGES];
__device__ float g_AX [(size_t)MROWS*64];      // [m=(n*8+t), 64] = [agg/deg | x]
__device__ float g_Wcat[HH*64];                // [128, 64] = [Wl | Wr]
__device__ float g_Wh [96*HH];                 // [96, 128] = [W_rec ; W_c1]
__device__ float g_bh [96];
__device__ float g_SP [(size_t)MROWS*HH];      // [m, 128]
__device__ float g_GX [(size_t)MROWS*3*HH];    // [m, 384]
__device__ float g_GH [(size_t)NNODES*3*HH];   // [n, 384]
__device__ float g_H  [(size_t)NNODES*HH];     // [n, 128]
__device__ float g_HS [(size_t)MROWS*HH];      // [m, 128]
__device__ float g_C1 [(size_t)MROWS*64];      // [m, 64]

// ======================= helpers =============================================
__device__ __forceinline__ float tf32_rna(float v) {
    uint32_t r;
    asm("cvt.rna.tf32.f32 %0, %1;" : "=r"(r) : "f"(v));
    return __uint_as_float(r);
}
#define MMA_TF32(C, Af, Bf) \
    asm volatile( \
        "mma.sync.aligned.m16n8k8.row.col.f32.tf32.tf32.f32 " \
        "{%0,%1,%2,%3}, {%4,%5,%6,%7}, {%8,%9}, {%0,%1,%2,%3};" \
        : "+f"((C)[0]), "+f"((C)[1]), "+f"((C)[2]), "+f"((C)[3]) \
        : "r"((Af)[0]), "r"((Af)[1]), "r"((Af)[2]), "r"((Af)[3]), \
          "r"((Bf)[0]), "r"((Bf)[1]))

// ======================= edge dtype detect + convert =========================
__global__ void detect_kernel(const void* ei) {
    const unsigned long long* p = (const unsigned long long*)ei;
    int is64 = 1;
    for (int i = 0; i < 1024; i++)
        if ((p[i] >> 32) != 0ull) { is64 = 0; break; }
    g_is64 = is64;
}
__global__ void convert_kernel(const void* ei) {
    int e = blockIdx.x * blockDim.x + threadIdx.x;
    if (e >= EDGES) return;
    int s, d;
    if (g_is64) {
        const long long* p = (const long long*)ei;
        s = (int)p[e]; d = (int)p[EDGES + e];
    } else {
        const int* p = (const int*)ei;
        s = p[e]; d = p[EDGES + e];
    }
    s = min(max(s, 0), NNODES - 1);
    d = min(max(d, 0), NNODES - 1);
    g_src[e] = s;
    g_dst[e] = d;
}

// ======================= graph prep ==========================================
__global__ void zero_kernel() {
    int idx = blockIdx.x * blockDim.x + threadIdx.x;
    int stride = gridDim.x * blockDim.x;
    for (size_t i = idx; i < (size_t)NNODES*HH; i += stride) g_H[i] = 0.f;
    for (int i = idx; i < NNODES; i += stride) g_cnt[i] = 0;
}
__global__ void count_kernel() {
    int e = blockIdx.x * blockDim.x + threadIdx.x;
    if (e < EDGES) atomicAdd(&g_cnt[g_dst[e]], 1);
}
__global__ void scan_kernel() {
    __shared__ int partial[1024];
    const int CH = (NNODES + 1023) / 1024;
    int t = threadIdx.x;
    int begin = t * CH;
    int end   = min(begin + CH, NNODES);
    int s = 0;
    for (int i = begin; i < end; i++) s += g_cnt[i];
    partial[t] = s;
    __syncthreads();
    #pragma unroll
    for (int d = 1; d < 1024; d <<= 1) {
        int v = (t >= d) ? partial[t - d] : 0;
        __syncthreads();
        partial[t] += v;
        __syncthreads();
    }
    int off = partial[t] - s;
    for (int i = begin; i < end; i++) {
        g_off[i] = off;
        g_cur[i] = off;
        off += g_cnt[i];
    }
}
__global__ void fill_kernel() {
    int e = blockIdx.x * blockDim.x + threadIdx.x;
    if (e >= EDGES) return;
    int pos = atomicAdd(&g_cur[g_dst[e]], 1);
    g_adj[pos] = g_src[e];
}
__global__ void __launch_bounds__(256) gather_kernel(const float* __restrict__ x) {
    int n   = blockIdx.x;
    int idx = threadIdx.x;
    int beg = g_off[n];
    int cnt = g_cnt[n];
    float s = 0.f;
    for (int p = beg; p < beg + cnt; p++) {
        int src = g_adj[p];
        s += x[(size_t)src * 256 + idx];
    }
    float dg = fmaxf((float)cnt, 1.f);
    int t = idx >> 5, c = idx & 31;
    size_t m = (size_t)n * 8 + t;
    g_AX[m * 64 + c]      = s / dg;
    g_AX[m * 64 + 32 + c] = x[(size_t)n * 256 + idx];
}
__global__ void wcat_kernel(const float* __restrict__ Wl, const float* __restrict__ Wr) {
    int idx = blockIdx.x * blockDim.x + threadIdx.x;
    if (idx >= HH*64) return;
    int j = idx >> 6, c = idx & 63;
    g_Wcat[idx] = (c < 32) ? Wl[j*32 + c] : Wr[j*32 + (c-32)];
}
__global__ void headcat_kernel(const float* __restrict__ W_rec, const float* __restrict__ b_rec,
                               const float* __restrict__ W_c1,  const float* __restrict__ b_c1) {
    int idx = blockIdx.x * blockDim.x + threadIdx.x;
    if (idx < 96*HH) {
        int r = idx >> 7, k = idx & 127;
        g_Wh[idx] = (r < 32) ? W_rec[r*128 + k] : W_c1[(r-32)*128 + k];
    }
    if (idx < 96) g_bh[idx] = (idx < 32) ? b_rec[idx] : b_c1[idx - 32];
}

// ======================= GRU pointwise =======================================
__global__ void gru_kernel(int t) {
    int idx = blockIdx.x * blockDim.x + threadIdx.x;
    if (idx >= NNODES*HH) return;
    int i = idx >> 7, j = idx & 127;
    size_t m = (size_t)i*8 + t;
    float gxr = g_GX[m*384 + j];
    float gxz = g_GX[m*384 + 128 + j];
    float gxn = g_GX[m*384 + 256 + j];
    float ghr = g_GH[(size_t)i*384 + j];
    float ghz = g_GH[(size_t)i*384 + 128 + j];
    float ghn = g_GH[(size_t)i*384 + 256 + j];
    float r  = 1.f / (1.f + expf(-(gxr + ghr)));
    float z  = 1.f / (1.f + expf(-(gxz + ghz)));
    float nn = tanhf(gxn + r*ghn);
    float h  = g_H[idx];
    float hn = (1.f - z)*nn + z*h;
    g_H[idx] = hn;
    g_HS[m*128 + j] = hn;
}

__global__ void cls_kernel(const float* __restrict__ w2, const float* __restrict__ b2,
                           float* __restrict__ out) {
    int g = blockIdx.x * blockDim.x + threadIdx.x;
    int warp = g >> 5;
    int lane = threadIdx.x & 31;
    if (warp >= MROWS) return;
    float s = g_C1[(size_t)warp*64 + lane]      * w2[lane]
            + g_C1[(size_t)warp*64 + 32 + lane] * w2[32 + lane];
    #pragma unroll
    for (int o = 16; o; o >>= 1) s += __shfl_xor_sync(0xffffffffu, s, o);
    if (lane == 0) out[warp] = 1.f / (1.f + expf(-(s + b2[0])));
}

// ======================= mma.sync 3xTF32 GEMM ================================
// C[m,n] = act( A[m,:].W[n,:] + bias[n] ), block tile 128x128, 512 thr (16 warps
// 4x4), warp tile 32x32 (2x4 m16n8k8 frags). K = KC*32 chunks through smem.
// fp32 accuracy via 3xTF32: C += Ahi*Bhi + Ahi*Blo + Alo*Bhi.
// ACT: 0 linear, 1 relu, 2 head-split (cols<32 linear->C ld32; 32..95 relu->C2 ld64)
#define SMS 129                        /* smem row stride: 8*129 % 32 = 8 */
#define SMQ (32*SMS)                   /* words per matrix buffer */
#define GSMEM (4*SMQ*4)                /* Ahi, Alo, Bhi, Blo */

template<int KC, int ACT>
__global__ void __launch_bounds__(512, 1) mma_gemm(
    int M, int nW,
    const float* __restrict__ A, int lda,
    const float* __restrict__ W, int ldw,
    const float* __restrict__ bias,
    float* __restrict__ C, int ldc,
    float* __restrict__ C2)
{
    extern __shared__ uint32_t smem[];
    uint32_t* Ah = smem;
    uint32_t* Al = smem + SMQ;
    uint32_t* Bh = smem + 2*SMQ;
    uint32_t* Bl = smem + 3*SMQ;

    const int tid  = threadIdx.x;
    const int lane = tid & 31;
    const int w    = tid >> 5;
    const int gid  = lane >> 2;     // group id 0..7
    const int tig  = lane & 3;      // thread-in-group
    const int wm   = w >> 2;        // warp row 0..3
    const int wn   = w & 3;         // warp col 0..3
    const int bm   = blockIdx.x * 128;
    const int bn   = blockIdx.y * 128;

    float acc[2][4][4];
    #pragma unroll
    for (int i = 0; i < 2; i++)
        #pragma unroll
        for (int j = 0; j < 4; j++)
            #pragma unroll
            for (int k = 0; k < 4; k++) acc[i][j][k] = 0.f;

    const int lrow = tid >> 2;      // 0..127 (smem row this thread fills)
    const int kq   = tid & 3;       // k-quad (8 floats each)

    for (int kc = 0; kc < KC; kc++) {
        if (kc) __syncthreads();

        // ---- fill A (hi/lo) ----
        {
            float v[8];
            int grow = bm + lrow;
            if (grow < M) {
                const float4* src = (const float4*)(A + (size_t)grow*lda + kc*32 + kq*8);
                float4 p0 = src[0], p1 = src[1];
                v[0]=p0.x; v[1]=p0.y; v[2]=p0.z; v[3]=p0.w;
                v[4]=p1.x; v[5]=p1.y; v[6]=p1.z; v[7]=p1.w;
            } else {
                #pragma unroll
                for (int i = 0; i < 8; i++) v[i] = 0.f;
            }
            #pragma unroll
            for (int i = 0; i < 8; i++) {
                float hi = tf32_rna(v[i]);
                float lo = tf32_rna(v[i] - hi);
                int kk = kq*8 + i;
                Ah[kk*SMS + lrow] = __float_as_uint(hi);
                Al[kk*SMS + lrow] = __float_as_uint(lo);
            }
        }
        // ---- fill B (hi/lo) ----
        {
            float v[8];
            int grow = bn + lrow;
            if (grow < nW) {
                const float4* src = (const float4*)(W + (size_t)grow*ldw + kc*32 + kq*8);
                float4 p0 = src[0], p1 = src[1];
                v[0]=p0.x; v[1]=p0.y; v[2]=p0.z; v[3]=p0.w;
                v[4]=p1.x; v[5]=p1.y; v[6]=p1.z; v[7]=p1.w;
            } else {
                #pragma unroll
                for (int i = 0; i < 8; i++) v[i] = 0.f;
            }
            #pragma unroll
            for (int i = 0; i < 8; i++) {
                float hi = tf32_rna(v[i]);
                float lo = tf32_rna(v[i] - hi);
                int kk = kq*8 + i;
                Bh[kk*SMS + lrow] = __float_as_uint(hi);
                Bl[kk*SMS + lrow] = __float_as_uint(lo);
            }
        }
        __syncthreads();

        // ---- 4 k8-steps of mma ----
        #pragma unroll
        for (int k8 = 0; k8 < 4; k8++) {
            const int k0 = k8*8;
            uint32_t afh[2][4], afl[2][4], bfh[4][2], bfl[4][2];
            #pragma unroll
            for (int mt = 0; mt < 2; mt++) {
                int r0 = wm*32 + mt*16 + gid;
                afh[mt][0] = Ah[(k0+tig  )*SMS + r0];
                afh[mt][1] = Ah[(k0+tig  )*SMS + r0 + 8];
                afh[mt][2] = Ah[(k0+tig+4)*SMS + r0];
                afh[mt][3] = Ah[(k0+tig+4)*SMS + r0 + 8];
                afl[mt][0] = Al[(k0+tig  )*SMS + r0];
                afl[mt][1] = Al[(k0+tig  )*SMS + r0 + 8];
                afl[mt][2] = Al[(k0+tig+4)*SMS + r0];
                afl[mt][3] = Al[(k0+tig+4)*SMS + r0 + 8];
            }
            #pragma unroll
            for (int nt = 0; nt < 4; nt++) {
                int cb = wn*32 + nt*8 + gid;
                bfh[nt][0] = Bh[(k0+tig  )*SMS + cb];
                bfh[nt][1] = Bh[(k0+tig+4)*SMS + cb];
                bfl[nt][0] = Bl[(k0+tig  )*SMS + cb];
                bfl[nt][1] = Bl[(k0+tig+4)*SMS + cb];
            }
            #pragma unroll
            for (int mt = 0; mt < 2; mt++)
                #pragma unroll
                for (int nt = 0; nt < 4; nt++) {
                    MMA_TF32(acc[mt][nt], afh[mt], bfh[nt]);
                    MMA_TF32(acc[mt][nt], afh[mt], bfl[nt]);
                    MMA_TF32(acc[mt][nt], afl[mt], bfh[nt]);
                }
        }
    }

    // ---- epilogue ----
    #pragma unroll
    for (int mt = 0; mt < 2; mt++) {
        #pragma unroll
        for (int nt = 0; nt < 4; nt++) {
            int col = bn + wn*32 + nt*8 + 2*tig;
            #pragma unroll
            for (int half = 0; half < 2; half++) {
                int row = bm + wm*32 + mt*16 + gid + half*8;
                if (row >= M) continue;
                float2 o;
                o.x = acc[mt][nt][half*2 + 0];
                o.y = acc[mt][nt][half*2 + 1];
                if (ACT == 2) {
                    if (col >= 96) continue;
                    o.x += bias[col];
                    o.y += bias[col + 1];
                    if (col < 32) {
                        *(float2*)(C + (size_t)row*32 + col) = o;
                    } else {
                        o.x = fmaxf(o.x, 0.f);
                        o.y = fmaxf(o.y, 0.f);
                        *(float2*)(C2 + (size_t)row*64 + col - 32) = o;
                    }
                } else {
                    o.x += bias[col];
                    o.y += bias[col + 1];
                    if (ACT == 1) {
                        o.x = fmaxf(o.x, 0.f);
                        o.y = fmaxf(o.y, 0.f);
                    }
                    *(float2*)(C + (size_t)row*ldc + col) = o;
                }
            }
        }
    }
}

// ======================= launch ==============================================
extern "C" void kernel_launch(void* const* d_in, const int* in_sizes, int n_in,
                              void* d_out, int out_size)
{
    const float* x     = (const float*)d_in[0];
    const void*  ei    = d_in[1];
    const float* Wl    = (const float*)d_in[2];
    const float* bl    = (const float*)d_in[3];
    const float* Wr    = (const float*)d_in[4];
    const float* W_ih  = (const float*)d_in[5];
    const float* b_ih  = (const float*)d_in[6];
    const float* W_hh  = (const float*)d_in[7];
    const float* b_hh  = (const float*)d_in[8];
    const float* W_rec = (const float*)d_in[9];
    const float* b_rec = (const float*)d_in[10];
    const float* W_c1  = (const float*)d_in[11];
    const float* b_c1  = (const float*)d_in[12];
    const float* W_c2  = (const float*)d_in[13];
    const float* b_c2  = (const float*)d_in[14];

    float* out      = (float*)d_out;
    float* outRecon = out;                          // [N,T,32] flat, row m
    float* outCls   = out + (size_t)MROWS * COUT;   // [N,T] flat, row m

    float *pAX, *pWcat, *pSP, *pGX, *pGH, *pH, *pHS, *pC1, *pWh, *pbh;
    cudaGetSymbolAddress((void**)&pAX,   g_AX);
    cudaGetSymbolAddress((void**)&pWcat, g_Wcat);
    cudaGetSymbolAddress((void**)&pSP,   g_SP);
    cudaGetSymbolAddress((void**)&pGX,   g_GX);
    cudaGetSymbolAddress((void**)&pGH,   g_GH);
    cudaGetSymbolAddress((void**)&pH,    g_H);
    cudaGetSymbolAddress((void**)&pHS,   g_HS);
    cudaGetSymbolAddress((void**)&pC1,   g_C1);
    cudaGetSymbolAddress((void**)&pWh,   g_Wh);
    cudaGetSymbolAddress((void**)&pbh,   g_bh);

    cudaFuncSetAttribute(mma_gemm<2,1>, cudaFuncAttributeMaxDynamicSharedMemorySize, GSMEM);
    cudaFuncSetAttribute(mma_gemm<4,0>, cudaFuncAttributeMaxDynamicSharedMemorySize, GSMEM);
    cudaFuncSetAttribute(mma_gemm<4,2>, cudaFuncAttributeMaxDynamicSharedMemorySize, GSMEM);

    // graph prep
    detect_kernel<<<1, 1>>>(ei);
    convert_kernel<<<(EDGES + 255)/256, 256>>>(ei);
    zero_kernel<<<1024, 256>>>();
    wcat_kernel<<<(HH*64 + 255)/256, 256>>>(Wl, Wr);
    headcat_kernel<<<(96*HH + 255)/256, 256>>>(W_rec, b_rec, W_c1, b_c1);
    count_kernel<<<(EDGES + 255)/256, 256>>>();
    scan_kernel<<<1, 1024>>>();
    fill_kernel<<<(EDGES + 255)/256, 256>>>();
    gather_kernel<<<NNODES, 256>>>(x);

    // SP = relu(AX @ Wcat^T + bl): [400000,64] -> [400000,128]
    mma_gemm<2,1><<<dim3(MROWS/128, 1), 512, GSMEM>>>(
        MROWS, 128, pAX, 64, pWcat, 64, bl, pSP, 128, nullptr);

    // GX = SP @ W_ih^T + b_ih: [400000,128] -> [400000,384]
    mma_gemm<4,0><<<dim3(MROWS/128, 3), 512, GSMEM>>>(
        MROWS, 384, pSP, 128, W_ih, 128, b_ih, pGX, 384, nullptr);

    // recurrence
    for (int t = 0; t < TT; t++) {
        mma_gemm<4,0><<<dim3((NNODES + 127)/128, 3), 512, GSMEM>>>(
            NNODES, 384, pH, 128, W_hh, 128, b_hh, pGH, 384, nullptr);
        gru_kernel<<<(NNODES*HH + 255)/256, 256>>>(t);
    }

    // heads: cols 0-31 linear -> recon (ld 32), cols 32-95 relu -> C1 (ld 64)
    mma_gemm<4,2><<<dim3(MROWS/128, 1), 512, GSMEM>>>(
        MROWS, 96, pHS, 128, pWh, 128, pbh, outRecon, 32, pC1);

    // cls = sigmoid(C1 @ w_c2 + b_c2)
    cls_kernel<<<(MROWS*32 + 255)/256, 256>>>(W_c2, b_c2, outCls);
}

// round 7
// speedup vs baseline: 1.6502x; 1.6502x over previous
#include <cuda_runtime.h>
#include <math.h>
#include <stdint.h>

#define NNODES 50000
#define TT 8
#define HH 128
#define COUT 32
#define EDGES 800000
#define MROWS 400000

// ======================= scratch (device globals) ============================
__device__ int   g_is64;
__device__ int   g_src[EDGES];
__device__ int   g_dst[EDGES];
__device__ int   g_cnt[NNODES];
__device__ int   g_off[NNODES];
__device__ int   g_cur[NNODES];
__device__ int   g_adj[EDGES];
__device__ float g_AX [(size_t)MROWS*64];      // [m=(n*8+t), 64] = [agg/deg | x]
__device__ float g_Wcat[HH*64];                // [128, 64] = [Wl | Wr]
__device__ float g_Wh [96*HH];                 // [96, 128] = [W_rec ; W_c1]
__device__ float g_bh [96];
__device__ float g_SP [(size_t)MROWS*HH];      // [m, 128]
__device__ float g_GX [(size_t)MROWS*3*HH];    // [m, 384]
__device__ float g_GH [(size_t)NNODES*3*HH];   // [n, 384]
__device__ float g_H  [(size_t)NNODES*HH];     // [n, 128]
__device__ float g_HS [(size_t)MROWS*HH];      // [m, 128]
__device__ float g_C1 [(size_t)MROWS*64];      // [m, 64]

// ======================= helpers =============================================
__device__ __forceinline__ float tf32_rna(float v) {
    uint32_t r;
    asm("cvt.rna.tf32.f32 %0, %1;" : "=r"(r) : "f"(v));
    return __uint_as_float(r);
}
#define MMA_TF32(C, Af, Bf) \
    asm volatile( \
        "mma.sync.aligned.m16n8k8.row.col.f32.tf32.tf32.f32 " \
        "{%0,%1,%2,%3}, {%4,%5,%6,%7}, {%8,%9}, {%0,%1,%2,%3};" \
        : "+f"((C)[0]), "+f"((C)[1]), "+f"((C)[2]), "+f"((C)[3]) \
        : "r"((Af)[0]), "r"((Af)[1]), "r"((Af)[2]), "r"((Af)[3]), \
          "r"((Bf)[0]), "r"((Bf)[1]))

// ======================= edge dtype detect + convert =========================
__global__ void detect_kernel(const void* ei) {
    const unsigned long long* p = (const unsigned long long*)ei;
    int is64 = 1;
    for (int i = 0; i < 1024; i++)
        if ((p[i] >> 32) != 0ull) { is64 = 0; break; }
    g_is64 = is64;
}
__global__ void convert_kernel(const void* ei) {
    int e = blockIdx.x * blockDim.x + threadIdx.x;
    if (e >= EDGES) return;
    int s, d;
    if (g_is64) {
        const long long* p = (const long long*)ei;
        s = (int)p[e]; d = (int)p[EDGES + e];
    } else {
        const int* p = (const int*)ei;
        s = p[e]; d = p[EDGES + e];
    }
    s = min(max(s, 0), NNODES - 1);
    d = min(max(d, 0), NNODES - 1);
    g_src[e] = s;
    g_dst[e] = d;
}

// ======================= graph prep ==========================================
__global__ void zero_kernel() {
    int idx = blockIdx.x * blockDim.x + threadIdx.x;
    int stride = gridDim.x * blockDim.x;
    for (size_t i = idx; i < (size_t)NNODES*HH; i += stride) g_H[i] = 0.f;
    for (int i = idx; i < NNODES; i += stride) g_cnt[i] = 0;
}
__global__ void count_kernel() {
    int e = blockIdx.x * blockDim.x + threadIdx.x;
    if (e < EDGES) atomicAdd(&g_cnt[g_dst[e]], 1);
}
__global__ void scan_kernel() {
    __shared__ int partial[1024];
    const int CH = (NNODES + 1023) / 1024;
    int t = threadIdx.x;
    int begin = t * CH;
    int end   = min(begin + CH, NNODES);
    int s = 0;
    for (int i = begin; i < end; i++) s += g_cnt[i];
    partial[t] = s;
    __syncthreads();
    #pragma unroll
    for (int d = 1; d < 1024; d <<= 1) {
        int v = (t >= d) ? partial[t - d] : 0;
        __syncthreads();
        partial[t] += v;
        __syncthreads();
    }
    int off = partial[t] - s;
    for (int i = begin; i < end; i++) {
        g_off[i] = off;
        g_cur[i] = off;
        off += g_cnt[i];
    }
}
__global__ void fill_kernel() {
    int e = blockIdx.x * blockDim.x + threadIdx.x;
    if (e >= EDGES) return;
    int pos = atomicAdd(&g_cur[g_dst[e]], 1);
    g_adj[pos] = g_src[e];
}
__global__ void __launch_bounds__(256) gather_kernel(const float* __restrict__ x) {
    int n   = blockIdx.x;
    int idx = threadIdx.x;
    int beg = g_off[n];
    int cnt = g_cnt[n];
    float s = 0.f;
    for (int p = beg; p < beg + cnt; p++) {
        int src = g_adj[p];
        s += x[(size_t)src * 256 + idx];
    }
    float dg = fmaxf((float)cnt, 1.f);
    int t = idx >> 5, c = idx & 31;
    size_t m = (size_t)n * 8 + t;
    g_AX[m * 64 + c]      = s / dg;
    g_AX[m * 64 + 32 + c] = x[(size_t)n * 256 + idx];
}
__global__ void wcat_kernel(const float* __restrict__ Wl, const float* __restrict__ Wr) {
    int idx = blockIdx.x * blockDim.x + threadIdx.x;
    if (idx >= HH*64) return;
    int j = idx >> 6, c = idx & 63;
    g_Wcat[idx] = (c < 32) ? Wl[j*32 + c] : Wr[j*32 + (c-32)];
}
__global__ void headcat_kernel(const float* __restrict__ W_rec, const float* __restrict__ b_rec,
                               const float* __restrict__ W_c1,  const float* __restrict__ b_c1) {
    int idx = blockIdx.x * blockDim.x + threadIdx.x;
    if (idx < 96*HH) {
        int r = idx >> 7, k = idx & 127;
        g_Wh[idx] = (r < 32) ? W_rec[r*128 + k] : W_c1[(r-32)*128 + k];
    }
    if (idx < 96) g_bh[idx] = (idx < 32) ? b_rec[idx] : b_c1[idx - 32];
}

// ======================= GRU pointwise =======================================
__global__ void gru_kernel(int t) {
    int idx = blockIdx.x * blockDim.x + threadIdx.x;
    if (idx >= NNODES*HH) return;
    int i = idx >> 7, j = idx & 127;
    size_t m = (size_t)i*8 + t;
    float gxr = g_GX[m*384 + j];
    float gxz = g_GX[m*384 + 128 + j];
    float gxn = g_GX[m*384 + 256 + j];
    float ghr = g_GH[(size_t)i*384 + j];
    float ghz = g_GH[(size_t)i*384 + 128 + j];
    float ghn = g_GH[(size_t)i*384 + 256 + j];
    float r  = 1.f / (1.f + expf(-(gxr + ghr)));
    float z  = 1.f / (1.f + expf(-(gxz + ghz)));
    float nn = tanhf(gxn + r*ghn);
    float h  = g_H[idx];
    float hn = (1.f - z)*nn + z*h;
    g_H[idx] = hn;
    g_HS[m*128 + j] = hn;
}

__global__ void cls_kernel(const float* __restrict__ w2, const float* __restrict__ b2,
                           float* __restrict__ out) {
    int g = blockIdx.x * blockDim.x + threadIdx.x;
    int warp = g >> 5;
    int lane = threadIdx.x & 31;
    if (warp >= MROWS) return;
    float s = g_C1[(size_t)warp*64 + lane]      * w2[lane]
            + g_C1[(size_t)warp*64 + 32 + lane] * w2[32 + lane];
    #pragma unroll
    for (int o = 16; o; o >>= 1) s += __shfl_xor_sync(0xffffffffu, s, o);
    if (lane == 0) out[warp] = 1.f / (1.f + expf(-(s + b2[0])));
}

// ======================= mma.sync 3xTF32 GEMM, cp.async pipelined ============
// C[m,n] = act( A[m,:].W[n,:] + bias[n] ); block tile 128x128, 512 thr (16 warps
// 4x4), warp tile 32x32 (2x4 m16n8k8 frags). K = KC*32, 2-stage cp.async pipe.
// SMEM holds RAW fp32; hi/lo tf32 split happens at fragment-load time.
// ACT: 0 linear, 1 relu, 2 head-split (cols<32 linear->C ld32; 32..95 relu->C2 ld64)
#define SROW 36                        /* words per smem row (32 + 4 pad) */
#define SMAT (128*SROW)                /* words per matrix tile: 4608 */
#define GSMEM (2*2*SMAT*4)             /* 2 stages x (A,B) = 73728 B */

template<int KC, int ACT>
__global__ void __launch_bounds__(512, 1) mma_gemm(
    int M, int nW,
    const float* __restrict__ A, int lda,
    const float* __restrict__ W, int ldw,
    const float* __restrict__ bias,
    float* __restrict__ C, int ldc,
    float* __restrict__ C2)
{
    extern __shared__ float smem[];
    uint32_t smem_b;
    asm("{ .reg .u64 t; cvta.to.shared.u64 t, %1; cvt.u32.u64 %0, t; }"
        : "=r"(smem_b) : "l"(smem));

    const int tid  = threadIdx.x;
    const int lane = tid & 31;
    const int w    = tid >> 5;
    const int gid  = lane >> 2;
    const int tig  = lane & 3;
    const int wm   = w >> 2;
    const int wn   = w & 3;
    const int bm   = blockIdx.x * 128;
    const int bn   = blockIdx.y * 128;

    float acc[2][4][4];
    #pragma unroll
    for (int i = 0; i < 2; i++)
        #pragma unroll
        for (int j = 0; j < 4; j++)
            #pragma unroll
            for (int k = 0; k < 4; k++) acc[i][j][k] = 0.f;

    // ---- async copy of one 128x32 chunk pair into stage (kc&1) ----
    auto issue_copy = [&](int kc) {
        const int s = kc & 1;
        const uint32_t abase = smem_b + (uint32_t)(s * 2 * SMAT) * 4u;
        const uint32_t bbase = abase + (uint32_t)SMAT * 4u;
        #pragma unroll
        for (int h = 0; h < 2; h++) {
            int i   = tid + h * 512;
            int row = i >> 3;
            int seg = i & 7;
            uint32_t soff = (uint32_t)(row * SROW + seg * 4) * 4u;
            {
                int grow = bm + row;
                const float* src = A + (size_t)min(grow, M - 1) * lda + kc * 32 + seg * 4;
                int sz = (grow < M) ? 16 : 0;
                asm volatile("cp.async.ca.shared.global [%0], [%1], 16, %2;"
                             :: "r"(abase + soff), "l"(src), "r"(sz));
            }
            {
                int grow = bn + row;
                const float* src = W + (size_t)min(grow, nW - 1) * ldw + kc * 32 + seg * 4;
                int sz = (grow < nW) ? 16 : 0;
                asm volatile("cp.async.ca.shared.global [%0], [%1], 16, %2;"
                             :: "r"(bbase + soff), "l"(src), "r"(sz));
            }
        }
        asm volatile("cp.async.commit_group;" ::: "memory");
    };

    issue_copy(0);

    for (int kc = 0; kc < KC; kc++) {
        if (kc + 1 < KC) {
            issue_copy(kc + 1);
            asm volatile("cp.async.wait_group 1;" ::: "memory");
        } else {
            asm volatile("cp.async.wait_group 0;" ::: "memory");
        }
        __syncthreads();

        const float* Af = smem + (kc & 1) * 2 * SMAT;
        const float* Bf = Af + SMAT;

        #pragma unroll
        for (int k8 = 0; k8 < 4; k8++) {
            const int k0 = k8 * 8;
            float ar[2][4], br[4][2];
            #pragma unroll
            for (int mt = 0; mt < 2; mt++) {
                int r0 = wm*32 + mt*16 + gid;
                ar[mt][0] = Af[ r0      *SROW + k0 + tig    ];
                ar[mt][1] = Af[(r0 + 8) *SROW + k0 + tig    ];
                ar[mt][2] = Af[ r0      *SROW + k0 + tig + 4];
                ar[mt][3] = Af[(r0 + 8) *SROW + k0 + tig + 4];
            }
            #pragma unroll
            for (int nt = 0; nt < 4; nt++) {
                int cb = wn*32 + nt*8 + gid;
                br[nt][0] = Bf[cb*SROW + k0 + tig    ];
                br[nt][1] = Bf[cb*SROW + k0 + tig + 4];
            }
            // hi/lo split in registers (lo fed raw: HW truncation error ~2^-23)
            uint32_t afh[2][4], afl[2][4], bfh[4][2], bfl[4][2];
            #pragma unroll
            for (int mt = 0; mt < 2; mt++)
                #pragma unroll
                for (int q = 0; q < 4; q++) {
                    float hi = tf32_rna(ar[mt][q]);
                    afh[mt][q] = __float_as_uint(hi);
                    afl[mt][q] = __float_as_uint(ar[mt][q] - hi);
                }
            #pragma unroll
            for (int nt = 0; nt < 4; nt++)
                #pragma unroll
                for (int q = 0; q < 2; q++) {
                    float hi = tf32_rna(br[nt][q]);
                    bfh[nt][q] = __float_as_uint(hi);
                    bfl[nt][q] = __float_as_uint(br[nt][q] - hi);
                }
            #pragma unroll
            for (int mt = 0; mt < 2; mt++)
                #pragma unroll
                for (int nt = 0; nt < 4; nt++) {
                    MMA_TF32(acc[mt][nt], afh[mt], bfh[nt]);
                    MMA_TF32(acc[mt][nt], afh[mt], bfl[nt]);
                    MMA_TF32(acc[mt][nt], afl[mt], bfh[nt]);
                }
        }
        __syncthreads();
    }

    // ---- epilogue ----
    #pragma unroll
    for (int mt = 0; mt < 2; mt++) {
        #pragma unroll
        for (int nt = 0; nt < 4; nt++) {
            int col = bn + wn*32 + nt*8 + 2*tig;
            #pragma unroll
            for (int half = 0; half < 2; half++) {
                int row = bm + wm*32 + mt*16 + gid + half*8;
                if (row >= M) continue;
                float2 o;
                o.x = acc[mt][nt][half*2 + 0];
                o.y = acc[mt][nt][half*2 + 1];
                if (ACT == 2) {
                    if (col >= 96) continue;
                    o.x += bias[col];
                    o.y += bias[col + 1];
                    if (col < 32) {
                        *(float2*)(C + (size_t)row*32 + col) = o;
                    } else {
                        o.x = fmaxf(o.x, 0.f);
                        o.y = fmaxf(o.y, 0.f);
                        *(float2*)(C2 + (size_t)row*64 + col - 32) = o;
                    }
                } else {
                    o.x += bias[col];
                    o.y += bias[col + 1];
                    if (ACT == 1) {
                        o.x = fmaxf(o.x, 0.f);
                        o.y = fmaxf(o.y, 0.f);
                    }
                    *(float2*)(C + (size_t)row*ldc + col) = o;
                }
            }
        }
    }
}

// ======================= launch ==============================================
extern "C" void kernel_launch(void* const* d_in, const int* in_sizes, int n_in,
                              void* d_out, int out_size)
{
    const float* x     = (const float*)d_in[0];
    const void*  ei    = d_in[1];
    const float* Wl    = (const float*)d_in[2];
    const float* bl    = (const float*)d_in[3];
    const float* Wr    = (const float*)d_in[4];
    const float* W_ih  = (const float*)d_in[5];
    const float* b_ih  = (const float*)d_in[6];
    const float* W_hh  = (const float*)d_in[7];
    const float* b_hh  = (const float*)d_in[8];
    const float* W_rec = (const float*)d_in[9];
    const float* b_rec = (const float*)d_in[10];
    const float* W_c1  = (const float*)d_in[11];
    const float* b_c1  = (const float*)d_in[12];
    const float* W_c2  = (const float*)d_in[13];
    const float* b_c2  = (const float*)d_in[14];

    float* out      = (float*)d_out;
    float* outRecon = out;                          // [N,T,32] flat, row m
    float* outCls   = out + (size_t)MROWS * COUT;   // [N,T] flat, row m

    float *pAX, *pWcat, *pSP, *pGX, *pGH, *pH, *pHS, *pC1, *pWh, *pbh;
    cudaGetSymbolAddress((void**)&pAX,   g_AX);
    cudaGetSymbolAddress((void**)&pWcat, g_Wcat);
    cudaGetSymbolAddress((void**)&pSP,   g_SP);
    cudaGetSymbolAddress((void**)&pGX,   g_GX);
    cudaGetSymbolAddress((void**)&pGH,   g_GH);
    cudaGetSymbolAddress((void**)&pH,    g_H);
    cudaGetSymbolAddress((void**)&pHS,   g_HS);
    cudaGetSymbolAddress((void**)&pC1,   g_C1);
    cudaGetSymbolAddress((void**)&pWh,   g_Wh);
    cudaGetSymbolAddress((void**)&pbh,   g_bh);

    cudaFuncSetAttribute(mma_gemm<2,1>, cudaFuncAttributeMaxDynamicSharedMemorySize, GSMEM);
    cudaFuncSetAttribute(mma_gemm<4,0>, cudaFuncAttributeMaxDynamicSharedMemorySize, GSMEM);
    cudaFuncSetAttribute(mma_gemm<4,2>, cudaFuncAttributeMaxDynamicSharedMemorySize, GSMEM);

    // graph prep
    detect_kernel<<<1, 1>>>(ei);
    convert_kernel<<<(EDGES + 255)/256, 256>>>(ei);
    zero_kernel<<<1024, 256>>>();
    wcat_kernel<<<(HH*64 + 255)/256, 256>>>(Wl, Wr);
    headcat_kernel<<<(96*HH + 255)/256, 256>>>(W_rec, b_rec, W_c1, b_c1);
    count_kernel<<<(EDGES + 255)/256, 256>>>();
    scan_kernel<<<1, 1024>>>();
    fill_kernel<<<(EDGES + 255)/256, 256>>>();
    gather_kernel<<<NNODES, 256>>>(x);

    // SP = relu(AX @ Wcat^T + bl): [400000,64] -> [400000,128]
    mma_gemm<2,1><<<dim3(MROWS/128, 1), 512, GSMEM>>>(
        MROWS, 128, pAX, 64, pWcat, 64, bl, pSP, 128, nullptr);

    // GX = SP @ W_ih^T + b_ih: [400000,128] -> [400000,384]
    mma_gemm<4,0><<<dim3(MROWS/128, 3), 512, GSMEM>>>(
        MROWS, 384, pSP, 128, W_ih, 128, b_ih, pGX, 384, nullptr);

    // recurrence
    for (int t = 0; t < TT; t++) {
        mma_gemm<4,0><<<dim3((NNODES + 127)/128, 3), 512, GSMEM>>>(
            NNODES, 384, pH, 128, W_hh, 128, b_hh, pGH, 384, nullptr);
        gru_kernel<<<(NNODES*HH + 255)/256, 256>>>(t);
    }

    // heads: cols 0-31 linear -> recon (ld 32), cols 32-95 relu -> C1 (ld 64)
    mma_gemm<4,2><<<dim3(MROWS/128, 1), 512, GSMEM>>>(
        MROWS, 96, pHS, 128, pWh, 128, pbh, outRecon, 32, pC1);

    // cls = sigmoid(C1 @ w_c2 + b_c2)
    cls_kernel<<<(MROWS*32 + 255)/256, 256>>>(W_c2, b_c2, outCls);
}